// round 4
// baseline (speedup 1.0000x reference)
#include <cuda_runtime.h>
#include <cuda_bf16.h>
#include <cstdint>

// Problem dims
#define BB 8
#define SS 1024          // IMG*IMG
#define EE 768           // D_EMBED == D_MODEL
#define NH 12
#define DD 64

// ---------------- scratch (device globals; no allocs allowed) ----------------
__device__ float g_q[BB * SS * EE];
__device__ float g_k[BB * SS * EE];
__device__ float g_v[BB * SS * EE];
__device__ float g_ctx[BB * SS * EE];

// =============================================================================
// tf32 helpers
// =============================================================================
__device__ __forceinline__ void split_tf32(float x, uint32_t& hi, uint32_t& lo) {
    asm("cvt.rna.tf32.f32 %0, %1;" : "=r"(hi) : "f"(x));
    float r = x - __uint_as_float(hi);
    asm("cvt.rna.tf32.f32 %0, %1;" : "=r"(lo) : "f"(r));
}
__device__ __forceinline__ void split_tf32_f(float x, float& hi, float& lo) {
    uint32_t h, l; split_tf32(x, h, l);
    hi = __uint_as_float(h); lo = __uint_as_float(l);
}

__device__ __forceinline__ void mma_tf32(float* d, const uint32_t* a, const uint32_t* b) {
    asm volatile(
        "mma.sync.aligned.m16n8k8.row.col.f32.tf32.tf32.f32 "
        "{%0,%1,%2,%3}, {%4,%5,%6,%7}, {%8,%9}, {%0,%1,%2,%3};"
        : "+f"(d[0]), "+f"(d[1]), "+f"(d[2]), "+f"(d[3])
        : "r"(a[0]), "r"(a[1]), "r"(a[2]), "r"(a[3]),
          "r"(b[0]), "r"(b[1]));
}
#define F2U(p) (*(const uint32_t*)&(p))

// =============================================================================
// Kernel 1: QKV projection via 3xtf32 mma, staged hi/lo in smem (round 3).
// =============================================================================
#define GP_AP 136
#define GP_BP 36
#define GP_AH 0
#define GP_AL 4352
#define GP_BH 8704
#define GP_BL 11008
#define GP_SMEM_FLOATS 13312
#define GP_SMEM_BYTES (GP_SMEM_FLOATS * 4)

__global__ __launch_bounds__(256) void proj_mma_kernel(
    const float* __restrict__ xq, const float* __restrict__ xk, const float* __restrict__ xv,
    const float* __restrict__ wq, const float* __restrict__ wk, const float* __restrict__ wv,
    const float* __restrict__ bq, const float* __restrict__ bk, const float* __restrict__ bv)
{
    extern __shared__ float sp[];
    float* AH = sp + GP_AH;
    float* AL = sp + GP_AL;
    float* BH = sp + GP_BH;
    float* BL = sp + GP_BL;

    const int mat = blockIdx.z >> 3;
    const int b   = blockIdx.z & 7;

    const float* x; const float* w; const float* bi; float* y;
    if (mat == 0)      { x = xq; w = wq; bi = bq; y = g_q; }
    else if (mat == 1) { x = xk; w = wk; bi = bk; y = g_k; }
    else               { x = xv; w = wv; bi = bv; y = g_v; }
    x += (size_t)b * EE * SS;
    y += (size_t)b * SS * EE;

    const int m0 = blockIdx.x * 128;
    const int n0 = blockIdx.y * 64;

    const int tid  = threadIdx.x;
    const int lane = tid & 31;
    const int w8   = tid >> 5;
    const int wm   = w8 >> 1;
    const int wn   = w8 & 1;
    const int gid  = lane >> 2;
    const int ctid = lane & 3;

    float acc[2][4][4];
    #pragma unroll
    for (int i = 0; i < 2; i++)
        #pragma unroll
        for (int j = 0; j < 4; j++)
            #pragma unroll
            for (int q = 0; q < 4; q++) acc[i][j][q] = 0.f;

    for (int kg = 0; kg < EE; kg += 32) {
        __syncthreads();
        #pragma unroll
        for (int p = 0; p < 4; p++) {
            int idx = tid + p * 256;
            int kr  = idx >> 5;
            int mc  = (idx & 31) << 2;
            float4 v4 = *(const float4*)(x + (size_t)(kg + kr) * SS + m0 + mc);
            float h, l;
            split_tf32_f(v4.x, h, l); AH[kr*GP_AP + mc + 0] = h; AL[kr*GP_AP + mc + 0] = l;
            split_tf32_f(v4.y, h, l); AH[kr*GP_AP + mc + 1] = h; AL[kr*GP_AP + mc + 1] = l;
            split_tf32_f(v4.z, h, l); AH[kr*GP_AP + mc + 2] = h; AL[kr*GP_AP + mc + 2] = l;
            split_tf32_f(v4.w, h, l); AH[kr*GP_AP + mc + 3] = h; AL[kr*GP_AP + mc + 3] = l;
        }
        #pragma unroll
        for (int p = 0; p < 2; p++) {
            int idx = tid + p * 256;
            int r   = idx >> 3;
            int kc  = (idx & 7) << 2;
            float4 v4 = *(const float4*)(w + (size_t)(n0 + r) * EE + kg + kc);
            float h, l;
            split_tf32_f(v4.x, h, l); BH[r*GP_BP + kc + 0] = h; BL[r*GP_BP + kc + 0] = l;
            split_tf32_f(v4.y, h, l); BH[r*GP_BP + kc + 1] = h; BL[r*GP_BP + kc + 1] = l;
            split_tf32_f(v4.z, h, l); BH[r*GP_BP + kc + 2] = h; BL[r*GP_BP + kc + 2] = l;
            split_tf32_f(v4.w, h, l); BH[r*GP_BP + kc + 3] = h; BL[r*GP_BP + kc + 3] = l;
        }
        __syncthreads();

        #pragma unroll
        for (int k0 = 0; k0 < 32; k0 += 8) {
            uint32_t ah[2][4], al[2][4];
            #pragma unroll
            for (int mt = 0; mt < 2; mt++) {
                int mrow = wm * 32 + mt * 16 + gid;
                const float* ph = AH + (k0 + ctid) * GP_AP + mrow;
                const float* pl = AL + (k0 + ctid) * GP_AP + mrow;
                ah[mt][0] = F2U(ph[0]);          ah[mt][1] = F2U(ph[8]);
                ah[mt][2] = F2U(ph[4*GP_AP]);    ah[mt][3] = F2U(ph[4*GP_AP + 8]);
                al[mt][0] = F2U(pl[0]);          al[mt][1] = F2U(pl[8]);
                al[mt][2] = F2U(pl[4*GP_AP]);    al[mt][3] = F2U(pl[4*GP_AP + 8]);
            }
            #pragma unroll
            for (int nt = 0; nt < 4; nt++) {
                int nrow = wn * 32 + nt * 8 + gid;
                uint32_t bh[2], bl[2];
                bh[0] = F2U(BH[nrow*GP_BP + k0 + ctid]);
                bh[1] = F2U(BH[nrow*GP_BP + k0 + ctid + 4]);
                bl[0] = F2U(BL[nrow*GP_BP + k0 + ctid]);
                bl[1] = F2U(BL[nrow*GP_BP + k0 + ctid + 4]);
                #pragma unroll
                for (int mt = 0; mt < 2; mt++) {
                    mma_tf32(acc[mt][nt], ah[mt], bh);
                    mma_tf32(acc[mt][nt], ah[mt], bl);
                    mma_tf32(acc[mt][nt], al[mt], bh);
                }
            }
        }
    }

    #pragma unroll
    for (int nt = 0; nt < 4; nt++) {
        int col = n0 + wn * 32 + nt * 8 + 2 * ctid;
        float b0 = bi[col], b1 = bi[col + 1];
        #pragma unroll
        for (int mt = 0; mt < 2; mt++) {
            int row = m0 + wm * 32 + mt * 16 + gid;
            *(float2*)(y + (size_t)row * EE + col) =
                make_float2(acc[mt][nt][0] + b0, acc[mt][nt][1] + b1);
            *(float2*)(y + (size_t)(row + 8) * EE + col) =
                make_float2(acc[mt][nt][2] + b0, acc[mt][nt][3] + b1);
        }
    }
}

// =============================================================================
// Kernel 2: attention, fully staged hi/lo (round 4).
// Per block: (b, h, 32 q rows). 256 threads = 8 warps.
// smem (floats): QH[32][68] QL[32][68] | KH[128][68] KL[128][68] | Sc[32][1032]
// KH/KL reused for V chunks and for the ctx cross-warp reduction buffer.
// =============================================================================
#define AQP 68            // Q plane pitch
#define AKP 68            // K/V plane pitch
#define ASCP 1032         // Sc pitch
#define AQH_OFF 0
#define AQL_OFF 2176
#define AKH_OFF 4352
#define AKL_OFF 13056
#define ASC_OFF 21760
#define ATTN_SMEM_FLOATS 54784
#define ATTN_SMEM_BYTES (ATTN_SMEM_FLOATS * 4)   // 219136

__global__ __launch_bounds__(256) void attn_kernel(float* __restrict__ probs)
{
    extern __shared__ float sm[];
    float* QH = sm + AQH_OFF;
    float* QL = sm + AQL_OFF;
    float* KH = sm + AKH_OFF;
    float* KL = sm + AKL_OFF;
    float* Sc = sm + ASC_OFF;

    __shared__ float red[32][8];
    __shared__ float invs[32];

    const int tid  = threadIdx.x;
    const int lane = tid & 31;
    const int w    = tid >> 5;      // warp 0..7
    const int gid  = lane >> 2;     // 0..7
    const int ctid = lane & 3;      // 0..3

    const int qt = blockIdx.x;      // 0..31
    const int bh = blockIdx.y;      // 0..95
    const int b  = bh / NH;
    const int h  = bh % NH;

    const float* qptr  = g_q + ((size_t)b * SS + qt * 32) * EE + h * DD;
    const float* kbase = g_k + (size_t)b * SS * EE + h * DD;
    const float* vbase = g_v + (size_t)b * SS * EE + h * DD;

    // ---- stage Q (split once): 32 rows x 64 d ----
    #pragma unroll
    for (int p = 0; p < 2; p++) {
        int idx = tid + p * 256;
        int r   = idx >> 4;
        int d4  = (idx & 15) << 2;
        float4 v4 = *(const float4*)(qptr + (size_t)r * EE + d4);
        float4 h4, l4;
        split_tf32_f(v4.x, h4.x, l4.x);
        split_tf32_f(v4.y, h4.y, l4.y);
        split_tf32_f(v4.z, h4.z, l4.z);
        split_tf32_f(v4.w, h4.w, l4.w);
        *(float4*)(QH + r * AQP + d4) = h4;
        *(float4*)(QL + r * AQP + d4) = l4;
    }

    // =================== scores: S = (Q K^T)/8, 8 chunks of 128 k-rows =========
    for (int c = 0; c < 8; c++) {
        __syncthreads();   // Q staged (c=0) / prior chunk consumers done (c>0)
        const float* kptr = kbase + (size_t)(c * 128) * EE;
        #pragma unroll
        for (int p = 0; p < 8; p++) {
            int idx = tid + p * 256;      // 0..2047
            int r   = idx >> 4;           // 0..127
            int d4  = (idx & 15) << 2;
            float4 v4 = *(const float4*)(kptr + (size_t)r * EE + d4);
            float4 h4, l4;
            split_tf32_f(v4.x, h4.x, l4.x);
            split_tf32_f(v4.y, h4.y, l4.y);
            split_tf32_f(v4.z, h4.z, l4.z);
            split_tf32_f(v4.w, h4.w, l4.w);
            *(float4*)(KH + r * AKP + d4) = h4;
            *(float4*)(KL + r * AKP + d4) = l4;
        }
        __syncthreads();

        float acc[2][2][4];
        #pragma unroll
        for (int i = 0; i < 2; i++)
            #pragma unroll
            for (int j = 0; j < 2; j++)
                #pragma unroll
                for (int q = 0; q < 4; q++) acc[i][j][q] = 0.f;

        #pragma unroll
        for (int k0 = 0; k0 < 64; k0 += 8) {
            uint32_t ah[2][4], al[2][4];
            #pragma unroll
            for (int mt = 0; mt < 2; mt++) {
                const float* ph = QH + (mt * 16 + gid) * AQP + k0 + ctid;
                const float* pl = QL + (mt * 16 + gid) * AQP + k0 + ctid;
                ah[mt][0] = F2U(ph[0]);        ah[mt][1] = F2U(ph[8 * AQP]);
                ah[mt][2] = F2U(ph[4]);        ah[mt][3] = F2U(ph[8 * AQP + 4]);
                al[mt][0] = F2U(pl[0]);        al[mt][1] = F2U(pl[8 * AQP]);
                al[mt][2] = F2U(pl[4]);        al[mt][3] = F2U(pl[8 * AQP + 4]);
            }
            #pragma unroll
            for (int nt = 0; nt < 2; nt++) {
                int ncol = w * 16 + nt * 8 + gid;
                uint32_t bh_[2], bl_[2];
                bh_[0] = F2U(KH[ncol * AKP + k0 + ctid]);
                bh_[1] = F2U(KH[ncol * AKP + k0 + ctid + 4]);
                bl_[0] = F2U(KL[ncol * AKP + k0 + ctid]);
                bl_[1] = F2U(KL[ncol * AKP + k0 + ctid + 4]);
                #pragma unroll
                for (int mt = 0; mt < 2; mt++) {
                    mma_tf32(acc[mt][nt], ah[mt], bh_);
                    mma_tf32(acc[mt][nt], ah[mt], bl_);
                    mma_tf32(acc[mt][nt], al[mt], bh_);
                }
            }
        }

        #pragma unroll
        for (int mt = 0; mt < 2; mt++)
            #pragma unroll
            for (int nt = 0; nt < 2; nt++) {
                int colb = c * 128 + w * 16 + nt * 8 + 2 * ctid;
                int r0   = mt * 16 + gid;
                *(float2*)(Sc + r0 * ASCP + colb) =
                    make_float2(acc[mt][nt][0] * 0.125f, acc[mt][nt][1] * 0.125f);
                *(float2*)(Sc + (r0 + 8) * ASCP + colb) =
                    make_float2(acc[mt][nt][2] * 0.125f, acc[mt][nt][3] * 0.125f);
            }
    }
    __syncthreads();

    // =================== softmax over 32 rows (float4, bank-safe stride) ======
    {
        const int row = tid >> 3;
        const int j   = tid & 7;
        float* sr = Sc + row * ASCP;

        float mx = -3.4e38f;
        #pragma unroll 8
        for (int i = 0; i < 32; i++) {
            float4 f4 = *(float4*)(sr + (j + 8 * i) * 4);
            mx = fmaxf(mx, fmaxf(fmaxf(f4.x, f4.y), fmaxf(f4.z, f4.w)));
        }
        red[row][j] = mx;
        __syncthreads();
        #pragma unroll
        for (int t = 0; t < 8; t++) mx = fmaxf(mx, red[row][t]);
        __syncthreads();

        float sum = 0.f;
        #pragma unroll 8
        for (int i = 0; i < 32; i++) {
            float4 f4 = *(float4*)(sr + (j + 8 * i) * 4);
            f4.x = __expf(f4.x - mx);
            f4.y = __expf(f4.y - mx);
            f4.z = __expf(f4.z - mx);
            f4.w = __expf(f4.w - mx);
            *(float4*)(sr + (j + 8 * i) * 4) = f4;
            sum += f4.x + f4.y + f4.z + f4.w;
        }
        red[row][j] = sum;
        __syncthreads();
        float s = 0.f;
        #pragma unroll
        for (int t = 0; t < 8; t++) s += red[row][t];
        if (j == 0) invs[row] = 1.f / s;
    }
    __syncthreads();

    // =================== normalized probs write (float4, coalesced) ==========
    {
        float4* pbase = (float4*)(probs + ((size_t)bh * SS + qt * 32) * SS);
        #pragma unroll 8
        for (int i = 0; i < 32; i++) {
            int idx4 = tid + i * 256;         // 0..8191
            int row  = idx4 >> 8;             // 256 float4 per row
            int c4   = idx4 & 255;
            float4 f4 = *(float4*)(Sc + row * ASCP + c4 * 4);
            float iv = invs[row];
            f4.x *= iv; f4.y *= iv; f4.z *= iv; f4.w *= iv;
            pbase[idx4] = f4;
        }
    }

    // =================== ctx = P @ V : warps = 2(n) x 4(k-split) ==============
    const int wn = w & 1;       // n half
    const int wk = w >> 1;      // k quarter within chunk

    float acc2[2][4][4];
    #pragma unroll
    for (int i = 0; i < 2; i++)
        #pragma unroll
        for (int j = 0; j < 4; j++)
            #pragma unroll
            for (int q = 0; q < 4; q++) acc2[i][j][q] = 0.f;

    for (int c = 0; c < 8; c++) {
        __syncthreads();   // prior chunk consumers done
        const float* vptr = vbase + (size_t)(c * 128) * EE;
        #pragma unroll
        for (int p = 0; p < 8; p++) {
            int idx = tid + p * 256;
            int r   = idx >> 4;
            int d4  = (idx & 15) << 2;
            float4 v4 = *(const float4*)(vptr + (size_t)r * EE + d4);
            float4 h4, l4;
            split_tf32_f(v4.x, h4.x, l4.x);
            split_tf32_f(v4.y, h4.y, l4.y);
            split_tf32_f(v4.z, h4.z, l4.z);
            split_tf32_f(v4.w, h4.w, l4.w);
            *(float4*)(KH + r * AKP + d4) = h4;
            *(float4*)(KL + r * AKP + d4) = l4;
        }
        __syncthreads();

        #pragma unroll
        for (int ks = 0; ks < 4; ks++) {
            int kkc = wk * 32 + ks * 8;       // k offset within chunk
            uint32_t ah[2][4], al[2][4];
            #pragma unroll
            for (int mt = 0; mt < 2; mt++) {
                const float* sb = Sc + (mt * 16 + gid) * ASCP + c * 128 + kkc;
                split_tf32(sb[ctid],               ah[mt][0], al[mt][0]);
                split_tf32(sb[8 * ASCP + ctid],    ah[mt][1], al[mt][1]);
                split_tf32(sb[ctid + 4],           ah[mt][2], al[mt][2]);
                split_tf32(sb[8 * ASCP + ctid+4],  ah[mt][3], al[mt][3]);
            }
            #pragma unroll
            for (int nt = 0; nt < 4; nt++) {
                int ncol = wn * 32 + nt * 8 + gid;
                uint32_t bh_[2], bl_[2];
                bh_[0] = F2U(KH[(kkc + ctid) * AKP + ncol]);
                bh_[1] = F2U(KH[(kkc + ctid + 4) * AKP + ncol]);
                bl_[0] = F2U(KL[(kkc + ctid) * AKP + ncol]);
                bl_[1] = F2U(KL[(kkc + ctid + 4) * AKP + ncol]);
                #pragma unroll
                for (int mt = 0; mt < 2; mt++) {
                    mma_tf32(acc2[mt][nt], ah[mt], bh_);
                    mma_tf32(acc2[mt][nt], ah[mt], bl_);
                    mma_tf32(acc2[mt][nt], al[mt], bh_);
                }
            }
        }
    }
    __syncthreads();   // all warps done reading KH/KL (V)

    // ---- cross-warp reduction: 4 k-partials, buffer reuses KH/KL region ----
    float* RB = sm + AKH_OFF;   // [4][32][68] = 8704 floats
    #pragma unroll
    for (int mt = 0; mt < 2; mt++)
        #pragma unroll
        for (int nt = 0; nt < 4; nt++) {
            int r0   = mt * 16 + gid;
            int colb = wn * 32 + nt * 8 + 2 * ctid;
            float* bp = RB + wk * (32 * AKP);
            *(float2*)(bp + r0 * AKP + colb) =
                make_float2(acc2[mt][nt][0], acc2[mt][nt][1]);
            *(float2*)(bp + (r0 + 8) * AKP + colb) =
                make_float2(acc2[mt][nt][2], acc2[mt][nt][3]);
        }
    __syncthreads();

    {
        int e0  = tid * 8;           // element in [32 x 64]
        int row = e0 >> 6;
        int col = e0 & 63;
        float r8[8];
        #pragma unroll
        for (int j = 0; j < 8; j++) r8[j] = 0.f;
        #pragma unroll
        for (int ww = 0; ww < 4; ww++) {
            const float* bp = RB + ww * (32 * AKP) + row * AKP + col;
            float4 x0 = *(const float4*)bp;
            float4 x1 = *(const float4*)(bp + 4);
            r8[0] += x0.x; r8[1] += x0.y; r8[2] += x0.z; r8[3] += x0.w;
            r8[4] += x1.x; r8[5] += x1.y; r8[6] += x1.z; r8[7] += x1.w;
        }
        float ci = invs[row];
        float* op = g_ctx + ((size_t)b * SS + qt * 32 + row) * EE + h * DD + col;
        *(float4*)op       = make_float4(r8[0]*ci, r8[1]*ci, r8[2]*ci, r8[3]*ci);
        *(float4*)(op + 4) = make_float4(r8[4]*ci, r8[5]*ci, r8[6]*ci, r8[7]*ci);
    }
}

// =============================================================================
// Kernel 3: output projection via 3xtf32 mma (round 3).
// =============================================================================
#define GF_AP 36
#define GF_AH 0
#define GF_AL 4608
#define GF_BH 9216
#define GF_BL 11520
#define GF_SMEM_FLOATS 13824
#define GF_SMEM_BYTES (GF_SMEM_FLOATS * 4)

__global__ __launch_bounds__(256) void fc_mma_kernel(
    const float* __restrict__ fcw, const float* __restrict__ fcb,
    float* __restrict__ out)
{
    extern __shared__ float sp[];
    float* AH = sp + GF_AH;
    float* AL = sp + GF_AL;
    float* BH = sp + GF_BH;
    float* BL = sp + GF_BL;

    const int b  = blockIdx.z;
    const int m0 = blockIdx.x * 128;
    const int n0 = blockIdx.y * 64;

    const float* ctx = g_ctx + (size_t)b * SS * EE;

    const int tid  = threadIdx.x;
    const int lane = tid & 31;
    const int w8   = tid >> 5;
    const int wm   = w8 >> 1;
    const int wn   = w8 & 1;
    const int gid  = lane >> 2;
    const int ctid = lane & 3;

    float acc[2][4][4];
    #pragma unroll
    for (int i = 0; i < 2; i++)
        #pragma unroll
        for (int j = 0; j < 4; j++)
            #pragma unroll
            for (int q = 0; q < 4; q++) acc[i][j][q] = 0.f;

    for (int kg = 0; kg < EE; kg += 32) {
        __syncthreads();
        #pragma unroll
        for (int p = 0; p < 4; p++) {
            int idx = tid + p * 256;
            int r   = idx >> 3;
            int kc  = (idx & 7) << 2;
            float4 v4 = *(const float4*)(fcw + (size_t)(m0 + r) * EE + kg + kc);
            float h, l;
            split_tf32_f(v4.x, h, l); AH[r*GF_AP + kc + 0] = h; AL[r*GF_AP + kc + 0] = l;
            split_tf32_f(v4.y, h, l); AH[r*GF_AP + kc + 1] = h; AL[r*GF_AP + kc + 1] = l;
            split_tf32_f(v4.z, h, l); AH[r*GF_AP + kc + 2] = h; AL[r*GF_AP + kc + 2] = l;
            split_tf32_f(v4.w, h, l); AH[r*GF_AP + kc + 3] = h; AL[r*GF_AP + kc + 3] = l;
        }
        #pragma unroll
        for (int p = 0; p < 2; p++) {
            int idx = tid + p * 256;
            int r   = idx >> 3;
            int kc  = (idx & 7) << 2;
            float4 v4 = *(const float4*)(ctx + (size_t)(n0 + r) * EE + kg + kc);
            float h, l;
            split_tf32_f(v4.x, h, l); BH[r*GF_AP + kc + 0] = h; BL[r*GF_AP + kc + 0] = l;
            split_tf32_f(v4.y, h, l); BH[r*GF_AP + kc + 1] = h; BL[r*GF_AP + kc + 1] = l;
            split_tf32_f(v4.z, h, l); BH[r*GF_AP + kc + 2] = h; BL[r*GF_AP + kc + 2] = l;
            split_tf32_f(v4.w, h, l); BH[r*GF_AP + kc + 3] = h; BL[r*GF_AP + kc + 3] = l;
        }
        __syncthreads();

        #pragma unroll
        for (int k0 = 0; k0 < 32; k0 += 8) {
            uint32_t ah[2][4], al[2][4];
            #pragma unroll
            for (int mt = 0; mt < 2; mt++) {
                int mrow = wm * 32 + mt * 16 + gid;
                const float* ph = AH + mrow * GF_AP + k0 + ctid;
                const float* pl = AL + mrow * GF_AP + k0 + ctid;
                ah[mt][0] = F2U(ph[0]);              ah[mt][1] = F2U(ph[8*GF_AP]);
                ah[mt][2] = F2U(ph[4]);              ah[mt][3] = F2U(ph[8*GF_AP + 4]);
                al[mt][0] = F2U(pl[0]);              al[mt][1] = F2U(pl[8*GF_AP]);
                al[mt][2] = F2U(pl[4]);              al[mt][3] = F2U(pl[8*GF_AP + 4]);
            }
            #pragma unroll
            for (int nt = 0; nt < 4; nt++) {
                int nrow = wn * 32 + nt * 8 + gid;
                uint32_t bh[2], bl[2];
                bh[0] = F2U(BH[nrow*GF_AP + k0 + ctid]);
                bh[1] = F2U(BH[nrow*GF_AP + k0 + ctid + 4]);
                bl[0] = F2U(BL[nrow*GF_AP + k0 + ctid]);
                bl[1] = F2U(BL[nrow*GF_AP + k0 + ctid + 4]);
                #pragma unroll
                for (int mt = 0; mt < 2; mt++) {
                    mma_tf32(acc[mt][nt], ah[mt], bh);
                    mma_tf32(acc[mt][nt], ah[mt], bl);
                    mma_tf32(acc[mt][nt], al[mt], bh);
                }
            }
        }
    }

    #pragma unroll
    for (int mt = 0; mt < 2; mt++) {
        int row = m0 + wm * 32 + mt * 16 + gid;
        float fb0 = fcb[row];
        float fb1 = fcb[row + 8];
        #pragma unroll
        for (int nt = 0; nt < 4; nt++) {
            int col = n0 + wn * 32 + nt * 8 + 2 * ctid;
            *(float2*)(out + ((size_t)b * EE + row) * SS + col) =
                make_float2(acc[mt][nt][0] + fb0, acc[mt][nt][1] + fb0);
            *(float2*)(out + ((size_t)b * EE + row + 8) * SS + col) =
                make_float2(acc[mt][nt][2] + fb1, acc[mt][nt][3] + fb1);
        }
    }
}

// =============================================================================
extern "C" void kernel_launch(void* const* d_in, const int* in_sizes, int n_in,
                              void* d_out, int out_size)
{
    const float* q_img = (const float*)d_in[0];
    const float* k_img = (const float*)d_in[1];
    const float* v_img = (const float*)d_in[2];
    const float* wq_w  = (const float*)d_in[3];
    const float* wq_b  = (const float*)d_in[4];
    const float* wk_w  = (const float*)d_in[5];
    const float* wk_b  = (const float*)d_in[6];
    const float* wv_w  = (const float*)d_in[7];
    const float* wv_b  = (const float*)d_in[8];
    const float* fc_w  = (const float*)d_in[9];
    const float* fc_b  = (const float*)d_in[10];

    float* out   = (float*)d_out;
    float* probs = out + (size_t)BB * EE * SS;   // tuple output: (out, probs)

    cudaFuncSetAttribute(proj_mma_kernel, cudaFuncAttributeMaxDynamicSharedMemorySize,
                         GP_SMEM_BYTES);
    cudaFuncSetAttribute(attn_kernel, cudaFuncAttributeMaxDynamicSharedMemorySize,
                         ATTN_SMEM_BYTES);
    cudaFuncSetAttribute(fc_mma_kernel, cudaFuncAttributeMaxDynamicSharedMemorySize,
                         GF_SMEM_BYTES);

    // 1) QKV projections (tf32 mma)
    proj_mma_kernel<<<dim3(SS / 128, EE / 64, 3 * BB), 256, GP_SMEM_BYTES>>>(
        q_img, k_img, v_img, wq_w, wk_w, wv_w, wq_b, wk_b, wv_b);

    // 2) attention (+ probs output)
    attn_kernel<<<dim3(SS / 32, BB * NH), 256, ATTN_SMEM_BYTES>>>(probs);

    // 3) output projection (tf32 mma)
    fc_mma_kernel<<<dim3(EE / 128, SS / 64, BB), 256, GF_SMEM_BYTES>>>(fc_w, fc_b, out);
}

// round 5
// speedup vs baseline: 1.1923x; 1.1923x over previous
#include <cuda_runtime.h>
#include <cuda_bf16.h>
#include <cstdint>

// Problem dims
#define BB 8
#define SS 1024          // IMG*IMG
#define EE 768           // D_EMBED == D_MODEL
#define NH 12
#define DD 64

// ---------------- scratch (device globals; no allocs allowed) ----------------
__device__ float g_q[BB * SS * EE];
__device__ float g_k[BB * SS * EE];
__device__ float g_v[BB * SS * EE];
__device__ float g_ctx[BB * SS * EE];

// =============================================================================
// tf32 helpers
// =============================================================================
__device__ __forceinline__ void split_tf32(float x, uint32_t& hi, uint32_t& lo) {
    asm("cvt.rna.tf32.f32 %0, %1;" : "=r"(hi) : "f"(x));
    float r = x - __uint_as_float(hi);
    asm("cvt.rna.tf32.f32 %0, %1;" : "=r"(lo) : "f"(r));
}
__device__ __forceinline__ void split_tf32_f(float x, float& hi, float& lo) {
    uint32_t h, l; split_tf32(x, h, l);
    hi = __uint_as_float(h); lo = __uint_as_float(l);
}

__device__ __forceinline__ void mma_tf32(float* d, const uint32_t* a, const uint32_t* b) {
    asm volatile(
        "mma.sync.aligned.m16n8k8.row.col.f32.tf32.tf32.f32 "
        "{%0,%1,%2,%3}, {%4,%5,%6,%7}, {%8,%9}, {%0,%1,%2,%3};"
        : "+f"(d[0]), "+f"(d[1]), "+f"(d[2]), "+f"(d[3])
        : "r"(a[0]), "r"(a[1]), "r"(a[2]), "r"(a[3]),
          "r"(b[0]), "r"(b[1]));
}
#define F2U(p) (*(const uint32_t*)&(p))

// =============================================================================
// Kernel 1: QKV projection via 3xtf32 mma (round 3, unchanged).
// =============================================================================
#define GP_AP 136
#define GP_BP 36
#define GP_AH 0
#define GP_AL 4352
#define GP_BH 8704
#define GP_BL 11008
#define GP_SMEM_FLOATS 13312
#define GP_SMEM_BYTES (GP_SMEM_FLOATS * 4)

__global__ __launch_bounds__(256) void proj_mma_kernel(
    const float* __restrict__ xq, const float* __restrict__ xk, const float* __restrict__ xv,
    const float* __restrict__ wq, const float* __restrict__ wk, const float* __restrict__ wv,
    const float* __restrict__ bq, const float* __restrict__ bk, const float* __restrict__ bv)
{
    extern __shared__ float sp[];
    float* AH = sp + GP_AH;
    float* AL = sp + GP_AL;
    float* BH = sp + GP_BH;
    float* BL = sp + GP_BL;

    const int mat = blockIdx.z >> 3;
    const int b   = blockIdx.z & 7;

    const float* x; const float* w; const float* bi; float* y;
    if (mat == 0)      { x = xq; w = wq; bi = bq; y = g_q; }
    else if (mat == 1) { x = xk; w = wk; bi = bk; y = g_k; }
    else               { x = xv; w = wv; bi = bv; y = g_v; }
    x += (size_t)b * EE * SS;
    y += (size_t)b * SS * EE;

    const int m0 = blockIdx.x * 128;
    const int n0 = blockIdx.y * 64;

    const int tid  = threadIdx.x;
    const int lane = tid & 31;
    const int w8   = tid >> 5;
    const int wm   = w8 >> 1;
    const int wn   = w8 & 1;
    const int gid  = lane >> 2;
    const int ctid = lane & 3;

    float acc[2][4][4];
    #pragma unroll
    for (int i = 0; i < 2; i++)
        #pragma unroll
        for (int j = 0; j < 4; j++)
            #pragma unroll
            for (int q = 0; q < 4; q++) acc[i][j][q] = 0.f;

    for (int kg = 0; kg < EE; kg += 32) {
        __syncthreads();
        #pragma unroll
        for (int p = 0; p < 4; p++) {
            int idx = tid + p * 256;
            int kr  = idx >> 5;
            int mc  = (idx & 31) << 2;
            float4 v4 = *(const float4*)(x + (size_t)(kg + kr) * SS + m0 + mc);
            float h, l;
            split_tf32_f(v4.x, h, l); AH[kr*GP_AP + mc + 0] = h; AL[kr*GP_AP + mc + 0] = l;
            split_tf32_f(v4.y, h, l); AH[kr*GP_AP + mc + 1] = h; AL[kr*GP_AP + mc + 1] = l;
            split_tf32_f(v4.z, h, l); AH[kr*GP_AP + mc + 2] = h; AL[kr*GP_AP + mc + 2] = l;
            split_tf32_f(v4.w, h, l); AH[kr*GP_AP + mc + 3] = h; AL[kr*GP_AP + mc + 3] = l;
        }
        #pragma unroll
        for (int p = 0; p < 2; p++) {
            int idx = tid + p * 256;
            int r   = idx >> 3;
            int kc  = (idx & 7) << 2;
            float4 v4 = *(const float4*)(w + (size_t)(n0 + r) * EE + kg + kc);
            float h, l;
            split_tf32_f(v4.x, h, l); BH[r*GP_BP + kc + 0] = h; BL[r*GP_BP + kc + 0] = l;
            split_tf32_f(v4.y, h, l); BH[r*GP_BP + kc + 1] = h; BL[r*GP_BP + kc + 1] = l;
            split_tf32_f(v4.z, h, l); BH[r*GP_BP + kc + 2] = h; BL[r*GP_BP + kc + 2] = l;
            split_tf32_f(v4.w, h, l); BH[r*GP_BP + kc + 3] = h; BL[r*GP_BP + kc + 3] = l;
        }
        __syncthreads();

        #pragma unroll
        for (int k0 = 0; k0 < 32; k0 += 8) {
            uint32_t ah[2][4], al[2][4];
            #pragma unroll
            for (int mt = 0; mt < 2; mt++) {
                int mrow = wm * 32 + mt * 16 + gid;
                const float* ph = AH + (k0 + ctid) * GP_AP + mrow;
                const float* pl = AL + (k0 + ctid) * GP_AP + mrow;
                ah[mt][0] = F2U(ph[0]);          ah[mt][1] = F2U(ph[8]);
                ah[mt][2] = F2U(ph[4*GP_AP]);    ah[mt][3] = F2U(ph[4*GP_AP + 8]);
                al[mt][0] = F2U(pl[0]);          al[mt][1] = F2U(pl[8]);
                al[mt][2] = F2U(pl[4*GP_AP]);    al[mt][3] = F2U(pl[4*GP_AP + 8]);
            }
            #pragma unroll
            for (int nt = 0; nt < 4; nt++) {
                int nrow = wn * 32 + nt * 8 + gid;
                uint32_t bh[2], bl[2];
                bh[0] = F2U(BH[nrow*GP_BP + k0 + ctid]);
                bh[1] = F2U(BH[nrow*GP_BP + k0 + ctid + 4]);
                bl[0] = F2U(BL[nrow*GP_BP + k0 + ctid]);
                bl[1] = F2U(BL[nrow*GP_BP + k0 + ctid + 4]);
                #pragma unroll
                for (int mt = 0; mt < 2; mt++) {
                    mma_tf32(acc[mt][nt], ah[mt], bh);
                    mma_tf32(acc[mt][nt], ah[mt], bl);
                    mma_tf32(acc[mt][nt], al[mt], bh);
                }
            }
        }
    }

    #pragma unroll
    for (int nt = 0; nt < 4; nt++) {
        int col = n0 + wn * 32 + nt * 8 + 2 * ctid;
        float b0 = bi[col], b1 = bi[col + 1];
        #pragma unroll
        for (int mt = 0; mt < 2; mt++) {
            int row = m0 + wm * 32 + mt * 16 + gid;
            *(float2*)(y + (size_t)row * EE + col) =
                make_float2(acc[mt][nt][0] + b0, acc[mt][nt][1] + b1);
            *(float2*)(y + (size_t)(row + 8) * EE + col) =
                make_float2(acc[mt][nt][2] + b0, acc[mt][nt][3] + b1);
        }
    }
}

// =============================================================================
// Kernel 2a: scores GEMM.  S[q,k] = (Q . K^T) / 8  per (b,h), raw into probs.
// Tiles 128(m=q) x 64(n=k), K=64 staged once. A=Q[m][k], B=K[n][k], both
// k-contiguous, pitch-68 hi/lo planes.
// =============================================================================
#define SK_P 68
#define SK_AH 0
#define SK_AL 8704          // 128*68
#define SK_BH 17408
#define SK_BL 21760         // +64*68
#define SK_SMEM_FLOATS 26112
#define SK_SMEM_BYTES (SK_SMEM_FLOATS * 4)   // 104448

__global__ __launch_bounds__(256) void scores_mma_kernel(float* __restrict__ probs)
{
    extern __shared__ float sp[];
    float* AH = sp + SK_AH;
    float* AL = sp + SK_AL;
    float* BH = sp + SK_BH;
    float* BL = sp + SK_BL;

    const int bh = blockIdx.z;            // 0..95
    const int b  = bh / NH;
    const int h  = bh % NH;
    const int m0 = blockIdx.x * 128;      // q rows
    const int n0 = blockIdx.y * 64;       // k cols

    const float* qp = g_q + ((size_t)b * SS) * EE + h * DD;
    const float* kp = g_k + ((size_t)b * SS) * EE + h * DD;

    const int tid  = threadIdx.x;
    const int lane = tid & 31;
    const int w8   = tid >> 5;
    const int wm   = w8 >> 1;        // 0..3
    const int wn   = w8 & 1;         // 0..1
    const int gid  = lane >> 2;
    const int ctid = lane & 3;

    // stage A (Q): 128 rows x 64 k
    #pragma unroll
    for (int p = 0; p < 8; p++) {
        int idx = tid + p * 256;          // 0..2047 float4
        int r   = idx >> 4;
        int kc  = (idx & 15) << 2;
        float4 v4 = *(const float4*)(qp + (size_t)(m0 + r) * EE + kc);
        float4 h4, l4;
        split_tf32_f(v4.x, h4.x, l4.x);
        split_tf32_f(v4.y, h4.y, l4.y);
        split_tf32_f(v4.z, h4.z, l4.z);
        split_tf32_f(v4.w, h4.w, l4.w);
        *(float4*)(AH + r * SK_P + kc) = h4;
        *(float4*)(AL + r * SK_P + kc) = l4;
    }
    // stage B (K): 64 rows x 64 k
    #pragma unroll
    for (int p = 0; p < 4; p++) {
        int idx = tid + p * 256;          // 0..1023 float4
        int r   = idx >> 4;
        int kc  = (idx & 15) << 2;
        float4 v4 = *(const float4*)(kp + (size_t)(n0 + r) * EE + kc);
        float4 h4, l4;
        split_tf32_f(v4.x, h4.x, l4.x);
        split_tf32_f(v4.y, h4.y, l4.y);
        split_tf32_f(v4.z, h4.z, l4.z);
        split_tf32_f(v4.w, h4.w, l4.w);
        *(float4*)(BH + r * SK_P + kc) = h4;
        *(float4*)(BL + r * SK_P + kc) = l4;
    }
    __syncthreads();

    float acc[2][4][4];
    #pragma unroll
    for (int i = 0; i < 2; i++)
        #pragma unroll
        for (int j = 0; j < 4; j++)
            #pragma unroll
            for (int q = 0; q < 4; q++) acc[i][j][q] = 0.f;

    #pragma unroll
    for (int k0 = 0; k0 < 64; k0 += 8) {
        uint32_t ah[2][4], al[2][4];
        #pragma unroll
        for (int mt = 0; mt < 2; mt++) {
            int mrow = wm * 32 + mt * 16 + gid;
            const float* ph = AH + mrow * SK_P + k0 + ctid;
            const float* pl = AL + mrow * SK_P + k0 + ctid;
            ah[mt][0] = F2U(ph[0]);            ah[mt][1] = F2U(ph[8*SK_P]);
            ah[mt][2] = F2U(ph[4]);            ah[mt][3] = F2U(ph[8*SK_P + 4]);
            al[mt][0] = F2U(pl[0]);            al[mt][1] = F2U(pl[8*SK_P]);
            al[mt][2] = F2U(pl[4]);            al[mt][3] = F2U(pl[8*SK_P + 4]);
        }
        #pragma unroll
        for (int nt = 0; nt < 4; nt++) {
            int nrow = wn * 32 + nt * 8 + gid;
            uint32_t bh_[2], bl_[2];
            bh_[0] = F2U(BH[nrow*SK_P + k0 + ctid]);
            bh_[1] = F2U(BH[nrow*SK_P + k0 + ctid + 4]);
            bl_[0] = F2U(BL[nrow*SK_P + k0 + ctid]);
            bl_[1] = F2U(BL[nrow*SK_P + k0 + ctid + 4]);
            #pragma unroll
            for (int mt = 0; mt < 2; mt++) {
                mma_tf32(acc[mt][nt], ah[mt], bh_);
                mma_tf32(acc[mt][nt], ah[mt], bl_);
                mma_tf32(acc[mt][nt], al[mt], bh_);
            }
        }
    }

    // epilogue: raw scaled scores -> probs[(bh*SS + q)*SS + k]
    float* pbase = probs + (size_t)bh * SS * SS;
    #pragma unroll
    for (int mt = 0; mt < 2; mt++)
        #pragma unroll
        for (int nt = 0; nt < 4; nt++) {
            int row = m0 + wm * 32 + mt * 16 + gid;
            int col = n0 + wn * 32 + nt * 8 + 2 * ctid;
            *(float2*)(pbase + (size_t)row * SS + col) =
                make_float2(acc[mt][nt][0] * 0.125f, acc[mt][nt][1] * 0.125f);
            *(float2*)(pbase + (size_t)(row + 8) * SS + col) =
                make_float2(acc[mt][nt][2] * 0.125f, acc[mt][nt][3] * 0.125f);
        }
}

// =============================================================================
// Kernel 2b: in-place row softmax over probs. One warp per 1024-float row,
// fully register-resident, shfl reductions, no smem, no syncthreads.
// =============================================================================
__global__ __launch_bounds__(256) void softmax_kernel(float* __restrict__ probs)
{
    const int warp = threadIdx.x >> 5;
    const int lane = threadIdx.x & 31;
    const size_t row = (size_t)blockIdx.x * 8 + warp;   // 0 .. 96*1024-1

    float4* rp = (float4*)(probs + row * SS);

    float4 v[8];
    #pragma unroll
    for (int i = 0; i < 8; i++) v[i] = rp[lane + 32 * i];

    float mx = -3.4e38f;
    #pragma unroll
    for (int i = 0; i < 8; i++)
        mx = fmaxf(mx, fmaxf(fmaxf(v[i].x, v[i].y), fmaxf(v[i].z, v[i].w)));
    #pragma unroll
    for (int o = 16; o > 0; o >>= 1)
        mx = fmaxf(mx, __shfl_xor_sync(0xFFFFFFFFu, mx, o));

    float sum = 0.f;
    #pragma unroll
    for (int i = 0; i < 8; i++) {
        v[i].x = __expf(v[i].x - mx);
        v[i].y = __expf(v[i].y - mx);
        v[i].z = __expf(v[i].z - mx);
        v[i].w = __expf(v[i].w - mx);
        sum += v[i].x + v[i].y + v[i].z + v[i].w;
    }
    #pragma unroll
    for (int o = 16; o > 0; o >>= 1)
        sum += __shfl_xor_sync(0xFFFFFFFFu, sum, o);

    float inv = 1.f / sum;
    #pragma unroll
    for (int i = 0; i < 8; i++) {
        v[i].x *= inv; v[i].y *= inv; v[i].z *= inv; v[i].w *= inv;
        rp[lane + 32 * i] = v[i];
    }
}

// =============================================================================
// Kernel 2c: ctx GEMM.  ctx[q,d] = P[q,:] . V[:,d]  per (b,h).
// Tiles 128(m=q) x 64(n=d full), K=1024 in 32-chunks.
// A = probs[m][k] k-contig (pitch 36 planes); B = V[k][n] n-contig (pitch 68).
// =============================================================================
#define CX_AP 36
#define CX_BP 68
#define CX_AH 0
#define CX_AL 4608          // 128*36
#define CX_BH 9216
#define CX_BL 11392         // +32*68
#define CX_SMEM_FLOATS 13568
#define CX_SMEM_BYTES (CX_SMEM_FLOATS * 4)   // 54272

__global__ __launch_bounds__(256) void ctx_mma_kernel(const float* __restrict__ probs)
{
    extern __shared__ float sp[];
    float* AH = sp + CX_AH;
    float* AL = sp + CX_AL;
    float* BH = sp + CX_BH;
    float* BL = sp + CX_BL;

    const int bh = blockIdx.z;
    const int b  = bh / NH;
    const int h  = bh % NH;
    const int m0 = blockIdx.x * 128;     // q rows

    const float* pb = probs + (size_t)bh * SS * SS;
    const float* vb = g_v + ((size_t)b * SS) * EE + h * DD;

    const int tid  = threadIdx.x;
    const int lane = tid & 31;
    const int w8   = tid >> 5;
    const int wm   = w8 >> 1;        // 0..3
    const int wn   = w8 & 1;         // 0..1
    const int gid  = lane >> 2;
    const int ctid = lane & 3;

    float acc[2][4][4];
    #pragma unroll
    for (int i = 0; i < 2; i++)
        #pragma unroll
        for (int j = 0; j < 4; j++)
            #pragma unroll
            for (int q = 0; q < 4; q++) acc[i][j][q] = 0.f;

    for (int kg = 0; kg < SS; kg += 32) {
        __syncthreads();
        // stage A (probs): 128 rows x 32 k
        #pragma unroll
        for (int p = 0; p < 4; p++) {
            int idx = tid + p * 256;       // 0..1023 float4
            int r   = idx >> 3;
            int kc  = (idx & 7) << 2;
            float4 v4 = *(const float4*)(pb + (size_t)(m0 + r) * SS + kg + kc);
            float h4, l4;
            split_tf32_f(v4.x, h4, l4); AH[r*CX_AP + kc + 0] = h4; AL[r*CX_AP + kc + 0] = l4;
            split_tf32_f(v4.y, h4, l4); AH[r*CX_AP + kc + 1] = h4; AL[r*CX_AP + kc + 1] = l4;
            split_tf32_f(v4.z, h4, l4); AH[r*CX_AP + kc + 2] = h4; AL[r*CX_AP + kc + 2] = l4;
            split_tf32_f(v4.w, h4, l4); AH[r*CX_AP + kc + 3] = h4; AL[r*CX_AP + kc + 3] = l4;
        }
        // stage B (V): 32 k-rows x 64 d
        #pragma unroll
        for (int p = 0; p < 2; p++) {
            int idx = tid + p * 256;       // 0..511 float4
            int r   = idx >> 4;            // 0..31
            int d4  = (idx & 15) << 2;
            float4 v4 = *(const float4*)(vb + (size_t)(kg + r) * EE + d4);
            float4 h4, l4;
            split_tf32_f(v4.x, h4.x, l4.x);
            split_tf32_f(v4.y, h4.y, l4.y);
            split_tf32_f(v4.z, h4.z, l4.z);
            split_tf32_f(v4.w, h4.w, l4.w);
            *(float4*)(BH + r * CX_BP + d4) = h4;
            *(float4*)(BL + r * CX_BP + d4) = l4;
        }
        __syncthreads();

        #pragma unroll
        for (int k0 = 0; k0 < 32; k0 += 8) {
            uint32_t ah[2][4], al[2][4];
            #pragma unroll
            for (int mt = 0; mt < 2; mt++) {
                int mrow = wm * 32 + mt * 16 + gid;
                const float* ph = AH + mrow * CX_AP + k0 + ctid;
                const float* pl = AL + mrow * CX_AP + k0 + ctid;
                ah[mt][0] = F2U(ph[0]);            ah[mt][1] = F2U(ph[8*CX_AP]);
                ah[mt][2] = F2U(ph[4]);            ah[mt][3] = F2U(ph[8*CX_AP + 4]);
                al[mt][0] = F2U(pl[0]);            al[mt][1] = F2U(pl[8*CX_AP]);
                al[mt][2] = F2U(pl[4]);            al[mt][3] = F2U(pl[8*CX_AP + 4]);
            }
            #pragma unroll
            for (int nt = 0; nt < 4; nt++) {
                int ncol = wn * 32 + nt * 8 + gid;
                uint32_t bh_[2], bl_[2];
                bh_[0] = F2U(BH[(k0 + ctid) * CX_BP + ncol]);
                bh_[1] = F2U(BH[(k0 + ctid + 4) * CX_BP + ncol]);
                bl_[0] = F2U(BL[(k0 + ctid) * CX_BP + ncol]);
                bl_[1] = F2U(BL[(k0 + ctid + 4) * CX_BP + ncol]);
                #pragma unroll
                for (int mt = 0; mt < 2; mt++) {
                    mma_tf32(acc[mt][nt], ah[mt], bh_);
                    mma_tf32(acc[mt][nt], ah[mt], bl_);
                    mma_tf32(acc[mt][nt], al[mt], bh_);
                }
            }
        }
    }

    // epilogue: g_ctx[(b*SS + q)*EE + h*64 + d]
    #pragma unroll
    for (int mt = 0; mt < 2; mt++)
        #pragma unroll
        for (int nt = 0; nt < 4; nt++) {
            int row = m0 + wm * 32 + mt * 16 + gid;
            int col = wn * 32 + nt * 8 + 2 * ctid;
            float* op = g_ctx + ((size_t)b * SS + row) * EE + h * DD + col;
            *(float2*)op = make_float2(acc[mt][nt][0], acc[mt][nt][1]);
            *(float2*)(op + (size_t)8 * EE) = make_float2(acc[mt][nt][2], acc[mt][nt][3]);
        }
}

// =============================================================================
// Kernel 3: output projection via 3xtf32 mma (round 3, unchanged).
// =============================================================================
#define GF_AP 36
#define GF_AH 0
#define GF_AL 4608
#define GF_BH 9216
#define GF_BL 11520
#define GF_SMEM_FLOATS 13824
#define GF_SMEM_BYTES (GF_SMEM_FLOATS * 4)

__global__ __launch_bounds__(256) void fc_mma_kernel(
    const float* __restrict__ fcw, const float* __restrict__ fcb,
    float* __restrict__ out)
{
    extern __shared__ float sp[];
    float* AH = sp + GF_AH;
    float* AL = sp + GF_AL;
    float* BH = sp + GF_BH;
    float* BL = sp + GF_BL;

    const int b  = blockIdx.z;
    const int m0 = blockIdx.x * 128;
    const int n0 = blockIdx.y * 64;

    const float* ctx = g_ctx + (size_t)b * SS * EE;

    const int tid  = threadIdx.x;
    const int lane = tid & 31;
    const int w8   = tid >> 5;
    const int wm   = w8 >> 1;
    const int wn   = w8 & 1;
    const int gid  = lane >> 2;
    const int ctid = lane & 3;

    float acc[2][4][4];
    #pragma unroll
    for (int i = 0; i < 2; i++)
        #pragma unroll
        for (int j = 0; j < 4; j++)
            #pragma unroll
            for (int q = 0; q < 4; q++) acc[i][j][q] = 0.f;

    for (int kg = 0; kg < EE; kg += 32) {
        __syncthreads();
        #pragma unroll
        for (int p = 0; p < 4; p++) {
            int idx = tid + p * 256;
            int r   = idx >> 3;
            int kc  = (idx & 7) << 2;
            float4 v4 = *(const float4*)(fcw + (size_t)(m0 + r) * EE + kg + kc);
            float h, l;
            split_tf32_f(v4.x, h, l); AH[r*GF_AP + kc + 0] = h; AL[r*GF_AP + kc + 0] = l;
            split_tf32_f(v4.y, h, l); AH[r*GF_AP + kc + 1] = h; AL[r*GF_AP + kc + 1] = l;
            split_tf32_f(v4.z, h, l); AH[r*GF_AP + kc + 2] = h; AL[r*GF_AP + kc + 2] = l;
            split_tf32_f(v4.w, h, l); AH[r*GF_AP + kc + 3] = h; AL[r*GF_AP + kc + 3] = l;
        }
        #pragma unroll
        for (int p = 0; p < 2; p++) {
            int idx = tid + p * 256;
            int r   = idx >> 3;
            int kc  = (idx & 7) << 2;
            float4 v4 = *(const float4*)(ctx + (size_t)(n0 + r) * EE + kg + kc);
            float h, l;
            split_tf32_f(v4.x, h, l); BH[r*GF_AP + kc + 0] = h; BL[r*GF_AP + kc + 0] = l;
            split_tf32_f(v4.y, h, l); BH[r*GF_AP + kc + 1] = h; BL[r*GF_AP + kc + 1] = l;
            split_tf32_f(v4.z, h, l); BH[r*GF_AP + kc + 2] = h; BL[r*GF_AP + kc + 2] = l;
            split_tf32_f(v4.w, h, l); BH[r*GF_AP + kc + 3] = h; BL[r*GF_AP + kc + 3] = l;
        }
        __syncthreads();

        #pragma unroll
        for (int k0 = 0; k0 < 32; k0 += 8) {
            uint32_t ah[2][4], al[2][4];
            #pragma unroll
            for (int mt = 0; mt < 2; mt++) {
                int mrow = wm * 32 + mt * 16 + gid;
                const float* ph = AH + mrow * GF_AP + k0 + ctid;
                const float* pl = AL + mrow * GF_AP + k0 + ctid;
                ah[mt][0] = F2U(ph[0]);              ah[mt][1] = F2U(ph[8*GF_AP]);
                ah[mt][2] = F2U(ph[4]);              ah[mt][3] = F2U(ph[8*GF_AP + 4]);
                al[mt][0] = F2U(pl[0]);              al[mt][1] = F2U(pl[8*GF_AP]);
                al[mt][2] = F2U(pl[4]);              al[mt][3] = F2U(pl[8*GF_AP + 4]);
            }
            #pragma unroll
            for (int nt = 0; nt < 4; nt++) {
                int nrow = wn * 32 + nt * 8 + gid;
                uint32_t bh[2], bl[2];
                bh[0] = F2U(BH[nrow*GF_AP + k0 + ctid]);
                bh[1] = F2U(BH[nrow*GF_AP + k0 + ctid + 4]);
                bl[0] = F2U(BL[nrow*GF_AP + k0 + ctid]);
                bl[1] = F2U(BL[nrow*GF_AP + k0 + ctid + 4]);
                #pragma unroll
                for (int mt = 0; mt < 2; mt++) {
                    mma_tf32(acc[mt][nt], ah[mt], bh);
                    mma_tf32(acc[mt][nt], ah[mt], bl);
                    mma_tf32(acc[mt][nt], al[mt], bh);
                }
            }
        }
    }

    #pragma unroll
    for (int mt = 0; mt < 2; mt++) {
        int row = m0 + wm * 32 + mt * 16 + gid;
        float fb0 = fcb[row];
        float fb1 = fcb[row + 8];
        #pragma unroll
        for (int nt = 0; nt < 4; nt++) {
            int col = n0 + wn * 32 + nt * 8 + 2 * ctid;
            *(float2*)(out + ((size_t)b * EE + row) * SS + col) =
                make_float2(acc[mt][nt][0] + fb0, acc[mt][nt][1] + fb0);
            *(float2*)(out + ((size_t)b * EE + row + 8) * SS + col) =
                make_float2(acc[mt][nt][2] + fb1, acc[mt][nt][3] + fb1);
        }
    }
}

// =============================================================================
extern "C" void kernel_launch(void* const* d_in, const int* in_sizes, int n_in,
                              void* d_out, int out_size)
{
    const float* q_img = (const float*)d_in[0];
    const float* k_img = (const float*)d_in[1];
    const float* v_img = (const float*)d_in[2];
    const float* wq_w  = (const float*)d_in[3];
    const float* wq_b  = (const float*)d_in[4];
    const float* wk_w  = (const float*)d_in[5];
    const float* wk_b  = (const float*)d_in[6];
    const float* wv_w  = (const float*)d_in[7];
    const float* wv_b  = (const float*)d_in[8];
    const float* fc_w  = (const float*)d_in[9];
    const float* fc_b  = (const float*)d_in[10];

    float* out   = (float*)d_out;
    float* probs = out + (size_t)BB * EE * SS;   // tuple output: (out, probs)

    cudaFuncSetAttribute(proj_mma_kernel, cudaFuncAttributeMaxDynamicSharedMemorySize,
                         GP_SMEM_BYTES);
    cudaFuncSetAttribute(scores_mma_kernel, cudaFuncAttributeMaxDynamicSharedMemorySize,
                         SK_SMEM_BYTES);
    cudaFuncSetAttribute(ctx_mma_kernel, cudaFuncAttributeMaxDynamicSharedMemorySize,
                         CX_SMEM_BYTES);
    cudaFuncSetAttribute(fc_mma_kernel, cudaFuncAttributeMaxDynamicSharedMemorySize,
                         GF_SMEM_BYTES);

    // 1) QKV projections (tf32 mma)
    proj_mma_kernel<<<dim3(SS / 128, EE / 64, 3 * BB), 256, GP_SMEM_BYTES>>>(
        q_img, k_img, v_img, wq_w, wk_w, wv_w, wq_b, wk_b, wv_b);

    // 2a) scores -> raw into probs buffer
    scores_mma_kernel<<<dim3(SS / 128, SS / 64, BB * NH), 256, SK_SMEM_BYTES>>>(probs);

    // 2b) in-place softmax over probs rows
    softmax_kernel<<<(BB * NH * SS) / 8, 256>>>(probs);

    // 2c) ctx = P @ V
    ctx_mma_kernel<<<dim3(SS / 128, 1, BB * NH), 256, CX_SMEM_BYTES>>>(probs);

    // 3) output projection (tf32 mma)
    fc_mma_kernel<<<dim3(EE / 128, SS / 64, BB), 256, GF_SMEM_BYTES>>>(fc_w, fc_b, out);
}